// round 2
// baseline (speedup 1.0000x reference)
#include <cuda_runtime.h>
#include <math.h>

#define B_    64
#define T_    256
#define F_IN_ 2048
#define H_    1024
#define G3    3072
#define SPLITS 16
#define KS    (H_ / SPLITS)   // 64

// ---------------- scratch (static device allocations; no cudaMalloc) ----------
__device__ float g_emb[B_ * T_ * H_];          //  64 MB
__device__ float g_gx [B_ * T_ * G3];          // 201 MB
__device__ float g_cp [SPLITS * B_ * G3];      // 12.6 MB split-K partials
__device__ float g_h  [B_ * H_];               // hidden state

// ---------------- init h0 = 0 -------------------------------------------------
__global__ void zero_h_kernel() {
    int i = blockIdx.x * blockDim.x + threadIdx.x;
    if (i < B_ * H_) g_h[i] = 0.f;
}

// ---------------- big SGEMM: C[M,N] = A[M,K] @ B[N,K]^T + bias[N] -------------
// BM=BN=128, BK=16, 8x8 micro, 256 threads. M,N % 128 == 0, K % 16 == 0.
__global__ __launch_bounds__(256) void sgemm_nt_bias(
    const float* __restrict__ A, const float* __restrict__ Bm,
    const float* __restrict__ bias, float* __restrict__ C,
    int M, int N, int K)
{
    __shared__ float As[16][128 + 4];
    __shared__ float Bs[16][128 + 4];
    const int tid = threadIdx.x;
    const int bm = blockIdx.y * 128;
    const int bn = blockIdx.x * 128;
    const int tx = tid & 15;   // 0..15 -> col micro
    const int ty = tid >> 4;   // 0..15 -> row micro

    float acc[8][8];
#pragma unroll
    for (int i = 0; i < 8; i++)
#pragma unroll
        for (int j = 0; j < 8; j++) acc[i][j] = 0.f;

    for (int k0 = 0; k0 < K; k0 += 16) {
#pragma unroll
        for (int l = 0; l < 2; l++) {
            int id = tid + l * 256;          // 0..511
            int r  = id >> 2;                // 0..127
            int c  = (id & 3) << 2;          // 0,4,8,12
            float4 va = *reinterpret_cast<const float4*>(&A[(size_t)(bm + r) * K + k0 + c]);
            As[c + 0][r] = va.x; As[c + 1][r] = va.y; As[c + 2][r] = va.z; As[c + 3][r] = va.w;
            float4 vb = *reinterpret_cast<const float4*>(&Bm[(size_t)(bn + r) * K + k0 + c]);
            Bs[c + 0][r] = vb.x; Bs[c + 1][r] = vb.y; Bs[c + 2][r] = vb.z; Bs[c + 3][r] = vb.w;
        }
        __syncthreads();
#pragma unroll
        for (int k = 0; k < 16; k++) {
            float ar[8], br[8];
            *reinterpret_cast<float4*>(ar)     = *reinterpret_cast<const float4*>(&As[k][ty * 8]);
            *reinterpret_cast<float4*>(ar + 4) = *reinterpret_cast<const float4*>(&As[k][ty * 8 + 4]);
            *reinterpret_cast<float4*>(br)     = *reinterpret_cast<const float4*>(&Bs[k][tx * 8]);
            *reinterpret_cast<float4*>(br + 4) = *reinterpret_cast<const float4*>(&Bs[k][tx * 8 + 4]);
#pragma unroll
            for (int i = 0; i < 8; i++)
#pragma unroll
                for (int j = 0; j < 8; j++)
                    acc[i][j] += ar[i] * br[j];
        }
        __syncthreads();
    }

    const int row0 = bm + ty * 8;
    const int col0 = bn + tx * 8;
    float bb[8];
#pragma unroll
    for (int j = 0; j < 8; j++) bb[j] = bias[col0 + j];
#pragma unroll
    for (int i = 0; i < 8; i++) {
        float4 v0, v1;
        v0.x = acc[i][0] + bb[0]; v0.y = acc[i][1] + bb[1];
        v0.z = acc[i][2] + bb[2]; v0.w = acc[i][3] + bb[3];
        v1.x = acc[i][4] + bb[4]; v1.y = acc[i][5] + bb[5];
        v1.z = acc[i][6] + bb[6]; v1.w = acc[i][7] + bb[7];
        *reinterpret_cast<float4*>(&C[(size_t)(row0 + i) * N + col0])     = v0;
        *reinterpret_cast<float4*>(&C[(size_t)(row0 + i) * N + col0 + 4]) = v1;
    }
}

// ---------------- per-step split-K GEMM: gh_partial = h @ w_hh^T --------------
// M=64 (batch), N=3072, K=1024 split into SPLITS chunks of KS.
// BM=64, BN=128, BK=16, 8x8 micro, 128 threads. grid = (24, SPLITS).
__global__ __launch_bounds__(128) void sgemm_step_splitk(const float* __restrict__ Whh)
{
    __shared__ float As[16][64 + 4];
    __shared__ float Bs[16][128 + 4];
    const int tid = threadIdx.x;
    const int bn = blockIdx.x * 128;
    const int s  = blockIdx.y;
    const int kbase = s * KS;
    const int tx = tid & 15;   // 0..15
    const int ty = tid >> 4;   // 0..7

    float acc[8][8];
#pragma unroll
    for (int i = 0; i < 8; i++)
#pragma unroll
        for (int j = 0; j < 8; j++) acc[i][j] = 0.f;

    for (int kk = 0; kk < KS; kk += 16) {
        const int k0 = kbase + kk;
#pragma unroll
        for (int l = 0; l < 2; l++) {        // A: 64x16 = 256 float4
            int id = tid + l * 128;
            int r  = id >> 2;                // 0..63
            int c  = (id & 3) << 2;
            float4 va = *reinterpret_cast<const float4*>(&g_h[r * H_ + k0 + c]);
            As[c + 0][r] = va.x; As[c + 1][r] = va.y; As[c + 2][r] = va.z; As[c + 3][r] = va.w;
        }
#pragma unroll
        for (int l = 0; l < 4; l++) {        // B: 128x16 = 512 float4
            int id = tid + l * 128;
            int r  = id >> 2;                // 0..127
            int c  = (id & 3) << 2;
            float4 vb = *reinterpret_cast<const float4*>(&Whh[(size_t)(bn + r) * H_ + k0 + c]);
            Bs[c + 0][r] = vb.x; Bs[c + 1][r] = vb.y; Bs[c + 2][r] = vb.z; Bs[c + 3][r] = vb.w;
        }
        __syncthreads();
#pragma unroll
        for (int k = 0; k < 16; k++) {
            float ar[8], br[8];
            *reinterpret_cast<float4*>(ar)     = *reinterpret_cast<const float4*>(&As[k][ty * 8]);
            *reinterpret_cast<float4*>(ar + 4) = *reinterpret_cast<const float4*>(&As[k][ty * 8 + 4]);
            *reinterpret_cast<float4*>(br)     = *reinterpret_cast<const float4*>(&Bs[k][tx * 8]);
            *reinterpret_cast<float4*>(br + 4) = *reinterpret_cast<const float4*>(&Bs[k][tx * 8 + 4]);
#pragma unroll
            for (int i = 0; i < 8; i++)
#pragma unroll
                for (int j = 0; j < 8; j++)
                    acc[i][j] += ar[i] * br[j];
        }
        __syncthreads();
    }

    const int row0 = ty * 8;
    const int col0 = bn + tx * 8;
    float* Cp = g_cp + (size_t)s * (B_ * G3);
#pragma unroll
    for (int i = 0; i < 8; i++) {
        float4 v0, v1;
        v0.x = acc[i][0]; v0.y = acc[i][1]; v0.z = acc[i][2]; v0.w = acc[i][3];
        v1.x = acc[i][4]; v1.y = acc[i][5]; v1.z = acc[i][6]; v1.w = acc[i][7];
        *reinterpret_cast<float4*>(&Cp[(size_t)(row0 + i) * G3 + col0])     = v0;
        *reinterpret_cast<float4*>(&Cp[(size_t)(row0 + i) * G3 + col0 + 4]) = v1;
    }
}

// ---------------- gate: reduce splits, GRU nonlinearity, mask, h & y ----------
__global__ __launch_bounds__(1024) void gru_gate_kernel(
    const float* __restrict__ gx, const float* __restrict__ b_hh,
    const int* __restrict__ lens, float* __restrict__ out, int t)
{
    const int idx = blockIdx.x * 1024 + threadIdx.x;  // 0..65535
    const int b = idx >> 10;
    const int j = idx & 1023;

    float ghr = 0.f, ghz = 0.f, ghn = 0.f;
#pragma unroll
    for (int s = 0; s < SPLITS; s++) {
        const float* base = g_cp + (size_t)s * (B_ * G3) + (size_t)b * G3;
        ghr += base[j];
        ghz += base[H_ + j];
        ghn += base[2 * H_ + j];
    }
    ghr += b_hh[j];
    ghz += b_hh[H_ + j];
    ghn += b_hh[2 * H_ + j];

    const float* gxb = gx + ((size_t)b * T_ + t) * G3;
    const float r = 1.f / (1.f + expf(-(gxb[j] + ghr)));
    const float z = 1.f / (1.f + expf(-(gxb[H_ + j] + ghz)));
    const float n = tanhf(gxb[2 * H_ + j] + r * ghn);

    const float hp = g_h[idx];
    const float hn = (1.f - z) * n + z * hp;
    const bool  m  = t < lens[b];
    g_h[idx] = m ? hn : hp;
    out[((size_t)b * T_ + t) * H_ + j] = m ? hn : 0.f;
}

// ---------------- hidden = output[:, T-1, :] ----------------------------------
__global__ void copy_hidden_kernel(float* __restrict__ out) {
    const int idx = blockIdx.x * 1024 + threadIdx.x;
    const int b = idx >> 10;
    const int j = idx & 1023;
    out[(size_t)B_ * T_ * H_ + idx] = out[((size_t)b * T_ + (T_ - 1)) * H_ + j];
}

// ---------------- launch ------------------------------------------------------
extern "C" void kernel_launch(void* const* d_in, const int* in_sizes, int n_in,
                              void* d_out, int out_size)
{
    const float* input = (const float*)d_in[0];
    const int*   lens  = (const int*)  d_in[1];
    const float* W_p   = (const float*)d_in[2];
    const float* b_p   = (const float*)d_in[3];
    const float* w_ih  = (const float*)d_in[4];
    const float* w_hh  = (const float*)d_in[5];
    const float* b_ih  = (const float*)d_in[6];
    const float* b_hh  = (const float*)d_in[7];
    float* out = (float*)d_out;

    float *emb, *gx;
    cudaGetSymbolAddress((void**)&emb, g_emb);
    cudaGetSymbolAddress((void**)&gx,  g_gx);

    // h0 = 0
    zero_h_kernel<<<64, 1024>>>();

    // emb = input @ W_p^T + b_p          [16384 x 1024], K=2048
    dim3 g1(H_ / 128, (B_ * T_) / 128);
    sgemm_nt_bias<<<g1, 256>>>(input, W_p, b_p, emb, B_ * T_, H_, F_IN_);

    // gx = emb @ w_ih^T + b_ih           [16384 x 3072], K=1024
    dim3 g2(G3 / 128, (B_ * T_) / 128);
    sgemm_nt_bias<<<g2, 256>>>(emb, w_ih, b_ih, gx, B_ * T_, G3, H_);

    // sequential GRU scan
    dim3 gs(G3 / 128, SPLITS);
    for (int t = 0; t < T_; t++) {
        sgemm_step_splitk<<<gs, 128>>>(w_hh);
        gru_gate_kernel<<<64, 1024>>>(gx, b_hh, lens, out, t);
    }

    copy_hidden_kernel<<<64, 1024>>>(out);
}